// round 1
// baseline (speedup 1.0000x reference)
#include <cuda_runtime.h>

#define N_NODES 10000
#define KK1 10
#define KK2 25
#define DIM 64
#define OUTD 128
#define NGRAPH 64

// Scratch (no allocations allowed): [a01(128) | mean_relu_a12(128)] per node0
__device__ float g_XR[N_NODES * 2 * OUTD];
__device__ float g_Seg[NGRAPH * OUTD];

// ---------------------------------------------------------------------------
// Kernel A: fused level-0 pipeline.
// Per node0: mean(h2) over K2 for each of K1 neighbors, build X (11 x 128):
//   rows 0..9  = [h1_j | mean_k h2_jk]
//   row 10     = [h0   | mean_j h1_j]
// Y = relu(X @ w0 + b0); emit a01 = Y[10], meanY = mean(Y[0..9]).
// w0 (64KB) resident in smem per persistent block.
// ---------------------------------------------------------------------------
extern "C" __global__ void __launch_bounds__(128, 3)
kA(const float* __restrict__ h0, const float* __restrict__ h1,
   const float* __restrict__ h2, const float* __restrict__ w0,
   const float* __restrict__ b0)
{
    extern __shared__ float sm[];
    float* w0s = sm;             // 16384 floats
    float* b0s = sm + 16384;     // 128
    float* Xs  = sm + 16512;     // 11*128 = 1408

    const int t = threadIdx.x;

    // Zero the segment accumulator (consumed by kB, which runs after kA).
    if (blockIdx.x < 16) {
        #pragma unroll
        for (int i = 0; i < 4; ++i)
            g_Seg[blockIdx.x * 512 + i * 128 + t] = 0.f;
    }

    // Stage w0 + b0 once per block.
    {
        const float4* w4 = (const float4*)w0;
        float4* s4 = (float4*)w0s;
        for (int i = t; i < 4096; i += 128) s4[i] = w4[i];
        b0s[t] = b0[t];
    }
    __syncthreads();

    const int c  = t & 63;   // column within 64-dim half
    const int jg = t >> 6;   // 0 or 1 -> j in [jg*5, jg*5+5)

    for (int n0 = blockIdx.x; n0 < N_NODES; n0 += gridDim.x) {
        // ---- Phase 1: stream h2, compute per-neighbor means; stage h1, h0 ----
        #pragma unroll
        for (int jj = 0; jj < 5; ++jj) {
            const int j = jg * 5 + jj;
            const float* p = h2 + (n0 * KK1 + j) * (KK2 * DIM) + c;
            float s = 0.f;
            #pragma unroll
            for (int k = 0; k < KK2; ++k) s += __ldg(p + k * DIM);
            Xs[j * 128 + 64 + c] = s * (1.f / 25.f);
            Xs[j * 128 + c]      = __ldg(h1 + (n0 * KK1 + j) * DIM + c);
        }
        if (t < 64) Xs[10 * 128 + t] = __ldg(h0 + n0 * DIM + t);
        __syncthreads();

        if (t < 64) {
            float s = 0.f;
            #pragma unroll
            for (int j = 0; j < KK1; ++j) s += Xs[j * 128 + t];
            Xs[10 * 128 + 64 + t] = s * 0.1f;
        }
        __syncthreads();

        // ---- Phase 2: Y(11x128) = relu(X @ w0 + b0), thread t owns column t ----
        float acc[11];
        #pragma unroll
        for (int r = 0; r < 11; ++r) acc[r] = 0.f;

        #pragma unroll 2
        for (int k = 0; k < 128; k += 4) {
            const float wa = w0s[(k + 0) * 128 + t];
            const float wb = w0s[(k + 1) * 128 + t];
            const float wc = w0s[(k + 2) * 128 + t];
            const float wd = w0s[(k + 3) * 128 + t];
            #pragma unroll
            for (int r = 0; r < 11; ++r) {
                const float4 x = *(const float4*)&Xs[r * 128 + k];
                acc[r] = fmaf(x.x, wa, acc[r]);
                acc[r] = fmaf(x.y, wb, acc[r]);
                acc[r] = fmaf(x.z, wc, acc[r]);
                acc[r] = fmaf(x.w, wd, acc[r]);
            }
        }

        const float bb = b0s[t];
        float ym = 0.f;
        #pragma unroll
        for (int r = 0; r < KK1; ++r) ym += fmaxf(acc[r] + bb, 0.f);
        const float a01 = fmaxf(acc[10] + bb, 0.f);

        g_XR[n0 * 256 + t]       = a01;
        g_XR[n0 * 256 + 128 + t] = ym * 0.1f;
        __syncthreads();   // protect Xs before next iteration
    }
}

// ---------------------------------------------------------------------------
// Kernel B: out = relu(XR @ w1 + b1) (10000 x 128), segment-sum via atomics.
// w1 (128KB) resident in smem; 256 threads process 2 rows per iteration.
// ---------------------------------------------------------------------------
extern "C" __global__ void __launch_bounds__(256, 1)
kB(const float* __restrict__ w1, const float* __restrict__ b1,
   const int* __restrict__ gid)
{
    extern __shared__ float sm[];
    float* w1s = sm;            // 32768 floats
    float* xs  = sm + 32768;    // 512 floats (2 rows)

    const int t = threadIdx.x;
    {
        const float4* w4 = (const float4*)w1;
        float4* s4 = (float4*)w1s;
        for (int i = t; i < 8192; i += 256) s4[i] = w4[i];
    }
    __syncthreads();

    const int per  = (N_NODES + gridDim.x - 1) / gridDim.x;
    const int r0   = blockIdx.x * per;
    const int rend = min(r0 + per, N_NODES);
    const int rsub = t >> 7;
    const int c    = t & 127;
    const float bb = __ldg(b1 + c);

    for (int rb = r0; rb < rend; rb += 2) {
        for (int e = t; e < 512; e += 256) {
            const int rr = rb + (e >> 8);
            xs[e] = (rr < rend) ? g_XR[rr * 256 + (e & 255)] : 0.f;
        }
        __syncthreads();

        const int row = rb + rsub;
        if (row < rend) {
            const float* x = xs + rsub * 256;
            float acc = bb;
            #pragma unroll 4
            for (int k = 0; k < 256; k += 4) {
                const float4 xv = *(const float4*)&x[k];
                acc = fmaf(xv.x, w1s[(k + 0) * 128 + c], acc);
                acc = fmaf(xv.y, w1s[(k + 1) * 128 + c], acc);
                acc = fmaf(xv.z, w1s[(k + 2) * 128 + c], acc);
                acc = fmaf(xv.w, w1s[(k + 3) * 128 + c], acc);
            }
            const float y = fmaxf(acc, 0.f);
            atomicAdd(&g_Seg[__ldg(gid + row) * OUTD + c], y);
        }
        __syncthreads();
    }
}

// ---------------------------------------------------------------------------
// Kernel C: readout MLP. r = selu(seg@wr1+br1); r = selu(r@wr2+br2); r@wr3+br3
// ---------------------------------------------------------------------------
extern "C" __global__ void __launch_bounds__(128, 1)
kC(const float* __restrict__ wr1, const float* __restrict__ br1,
   const float* __restrict__ wr2, const float* __restrict__ br2,
   const float* __restrict__ wr3, const float* __restrict__ br3,
   float* __restrict__ out)
{
    __shared__ float r1s[NGRAPH * 35];
    __shared__ float r2s[NGRAPH * 35];
    const int t = threadIdx.x;
    const float SC = 1.0507009873554805f;
    const float AL = 1.6732632423543772f;

    for (int task = t; task < NGRAPH * 35; task += 128) {
        const int g = task / 35, o = task % 35;
        float acc = br1[o];
        #pragma unroll 4
        for (int k = 0; k < OUTD; ++k)
            acc = fmaf(g_Seg[g * OUTD + k], wr1[k * 35 + o], acc);
        r1s[task] = (acc > 0.f) ? SC * acc : SC * AL * (expf(acc) - 1.f);
    }
    __syncthreads();

    for (int task = t; task < NGRAPH * 35; task += 128) {
        const int g = task / 35, o = task % 35;
        float acc = br2[o];
        #pragma unroll
        for (int k = 0; k < 35; ++k)
            acc = fmaf(r1s[g * 35 + k], wr2[k * 35 + o], acc);
        r2s[task] = (acc > 0.f) ? SC * acc : SC * AL * (expf(acc) - 1.f);
    }
    __syncthreads();

    if (t < NGRAPH) {
        float acc = br3[0];
        #pragma unroll
        for (int k = 0; k < 35; ++k)
            acc = fmaf(r2s[t * 35 + k], wr3[k], acc);
        out[t] = acc;
    }
}

// ---------------------------------------------------------------------------
extern "C" void kernel_launch(void* const* d_in, const int* in_sizes, int n_in,
                              void* d_out, int out_size)
{
    const float* h0  = (const float*)d_in[0];
    const float* h1  = (const float*)d_in[1];
    const float* h2  = (const float*)d_in[2];
    const float* w0  = (const float*)d_in[3];
    const float* b0  = (const float*)d_in[4];
    const float* w1  = (const float*)d_in[5];
    const float* b1  = (const float*)d_in[6];
    const float* wr1 = (const float*)d_in[7];
    const float* br1 = (const float*)d_in[8];
    const float* wr2 = (const float*)d_in[9];
    const float* br2 = (const float*)d_in[10];
    const float* wr3 = (const float*)d_in[11];
    const float* br3 = (const float*)d_in[12];
    const int*   gid = (const int*)d_in[13];

    const int smA = (16384 + 128 + 11 * 128) * 4;      // 71680 B
    const int smB = (32768 + 512) * 4;                 // 133120 B
    cudaFuncSetAttribute(kA, cudaFuncAttributeMaxDynamicSharedMemorySize, smA);
    cudaFuncSetAttribute(kB, cudaFuncAttributeMaxDynamicSharedMemorySize, smB);

    kA<<<444, 128, smA>>>(h0, h1, h2, w0, b0);
    kB<<<148, 256, smB>>>(w1, b1, gid);
    kC<<<1, 128>>>(wr1, br1, wr2, br2, wr3, br3, (float*)d_out);
}

// round 2
// speedup vs baseline: 1.5235x; 1.5235x over previous
#include <cuda_runtime.h>

#define N_NODES 10000
#define KK1 10
#define KK2 25
#define DIM 64
#define OUTD 128
#define NGRAPH 64

// Scratch: per node0 [a01(128) | mean_relu_a12(128)]
__device__ float g_XR[N_NODES * 256];
__device__ float g_Seg[NGRAPH * OUTD];

// ---------------------------------------------------------------------------
// Kernel A: fused level-0 pipeline. 256 threads, 2 nodes per iteration,
// one shared w0 copy per block -> 2 blocks/SM (16 warps).
// Phase 1 uses float4 column-group sums: 25 INDEPENDENT LDG.128 per task
// (high MLP) instead of 125 serial scalar loads.
// ---------------------------------------------------------------------------
extern "C" __global__ void __launch_bounds__(256, 2)
kA(const float* __restrict__ h0, const float* __restrict__ h1,
   const float* __restrict__ h2, const float* __restrict__ w0,
   const float* __restrict__ b0)
{
    extern __shared__ float sm[];
    float* w0s = sm;             // 16384 floats (w0: [128][128])
    float* b0s = sm + 16384;     // 128
    float* Xs  = sm + 16512;     // 2 nodes x 11*128 = 2816 floats

    const int t = threadIdx.x;

    // Zero segment accumulator (kB runs after kA completes).
    if (blockIdx.x < 32)
        g_Seg[blockIdx.x * 256 + t] = 0.f;

    // Stage w0 + b0 once per block.
    {
        const float4* w4 = (const float4*)w0;
        float4* s4 = (float4*)w0s;
        #pragma unroll
        for (int i = 0; i < 16; ++i) s4[t + i * 256] = w4[t + i * 256];
        if (t < 128) b0s[t] = b0[t];
    }
    __syncthreads();

    for (int np = blockIdx.x * 2; np < N_NODES; np += gridDim.x * 2) {
        // ---- Phase 1: h2 means (float4 per task) + h1 + h0 staging ----
        // 320 tasks: (node in {0,1}) x (j in 0..9) x (c4 in 0..15)
        #pragma unroll
        for (int pass = 0; pass < 2; ++pass) {
            const int task = t + pass * 256;
            if (task < 2 * KK1 * 16) {
                const int node = task / 160;
                const int rem  = task - node * 160;
                const int j    = rem >> 4;
                const int c4   = rem & 15;
                const int base = (np + node) * KK1 + j;
                const float4* p2 = (const float4*)(h2 + base * (KK2 * DIM)) + c4;
                float4 s = make_float4(0.f, 0.f, 0.f, 0.f);
                #pragma unroll
                for (int k = 0; k < KK2; ++k) {
                    const float4 v = __ldg(p2 + k * 16);
                    s.x += v.x; s.y += v.y; s.z += v.z; s.w += v.w;
                }
                float4* xrow = (float4*)(Xs + node * 1408 + j * 128);
                xrow[16 + c4] = make_float4(s.x * 0.04f, s.y * 0.04f,
                                            s.z * 0.04f, s.w * 0.04f);
                xrow[c4] = __ldg((const float4*)(h1 + base * DIM) + c4);
            }
        }
        if (t < 32) {
            const int node = t >> 4, c4 = t & 15;
            ((float4*)(Xs + node * 1408 + 10 * 128))[c4] =
                __ldg((const float4*)(h0 + (np + node) * DIM) + c4);
        }
        __syncthreads();

        // mean over h1 rows -> row 10, cols 64..127
        if (t < 128) {
            const int node = t >> 6, c = t & 63;
            float s = 0.f;
            #pragma unroll
            for (int j = 0; j < KK1; ++j) s += Xs[node * 1408 + j * 128 + c];
            Xs[node * 1408 + 10 * 128 + 64 + c] = s * 0.1f;
        }
        __syncthreads();

        // ---- Phase 2: Y(11x128) = relu(X @ w0 + b0) ----
        const int node = t >> 7, col = t & 127;
        const float* X = Xs + node * 1408;

        float acc[11];
        #pragma unroll
        for (int r = 0; r < 11; ++r) acc[r] = 0.f;

        #pragma unroll 2
        for (int k = 0; k < 128; k += 4) {
            const float wa = w0s[(k + 0) * 128 + col];
            const float wb = w0s[(k + 1) * 128 + col];
            const float wc = w0s[(k + 2) * 128 + col];
            const float wd = w0s[(k + 3) * 128 + col];
            #pragma unroll
            for (int r = 0; r < 11; ++r) {
                const float4 x = *(const float4*)&X[r * 128 + k];
                acc[r] = fmaf(x.x, wa, acc[r]);
                acc[r] = fmaf(x.y, wb, acc[r]);
                acc[r] = fmaf(x.z, wc, acc[r]);
                acc[r] = fmaf(x.w, wd, acc[r]);
            }
        }

        const float bb = b0s[col];
        float ym = 0.f;
        #pragma unroll
        for (int r = 0; r < KK1; ++r) ym += fmaxf(acc[r] + bb, 0.f);
        const float a01 = fmaxf(acc[10] + bb, 0.f);

        g_XR[(np + node) * 256 + col]       = a01;
        g_XR[(np + node) * 256 + 128 + col] = ym * 0.1f;
        __syncthreads();   // protect Xs for next iteration
    }
}

// ---------------------------------------------------------------------------
// Kernel B: out = relu(XR @ w1 + b1), segment-sum via atomics.
// N split in halves (64 cols/block) -> w1 half = 64KB smem -> 3 blocks/SM.
// 4 rows per iteration, 2-way split accumulator chain.
// ---------------------------------------------------------------------------
extern "C" __global__ void __launch_bounds__(256, 3)
kB(const float* __restrict__ w1, const float* __restrict__ b1,
   const int* __restrict__ gid)
{
    extern __shared__ float sm[];
    float* w1s = sm;            // 256*64 = 16384 floats
    float* xs  = sm + 16384;    // 4 rows * 256 = 1024 floats

    const int t     = threadIdx.x;
    const int half  = blockIdx.x & 1;
    const int bslot = blockIdx.x >> 1;
    const int cl    = t & 63;
    const int c     = cl + half * 64;
    const int rsub  = t >> 6;

    // Stage this block's 64-column slice of w1 ([256][128] row-major).
    for (int i = t; i < 256 * 16; i += 256) {
        const int k = i >> 4, q = i & 15;
        ((float4*)(w1s + k * 64))[q] =
            __ldg((const float4*)(w1 + k * 128 + half * 64) + q);
    }
    __syncthreads();

    const int nblocks = gridDim.x >> 1;
    const int per  = (N_NODES + nblocks - 1) / nblocks;
    const int r0   = bslot * per;
    const int rend = min(r0 + per, N_NODES);
    const float bb = __ldg(b1 + c);

    for (int rb = r0; rb < rend; rb += 4) {
        {
            const int rr = rb + (t >> 6);
            const int q  = t & 63;
            ((float4*)(xs + (t >> 6) * 256))[q] = (rr < rend)
                ? __ldg((const float4*)(g_XR + rr * 256) + q)
                : make_float4(0.f, 0.f, 0.f, 0.f);
        }
        __syncthreads();

        const int row = rb + rsub;
        if (row < rend) {
            const float* x = xs + rsub * 256;
            float a0 = 0.f, a1 = 0.f;
            #pragma unroll 4
            for (int k = 0; k < 256; k += 4) {
                const float4 xv = *(const float4*)&x[k];
                a0 = fmaf(xv.x, w1s[(k + 0) * 64 + cl], a0);
                a1 = fmaf(xv.y, w1s[(k + 1) * 64 + cl], a1);
                a0 = fmaf(xv.z, w1s[(k + 2) * 64 + cl], a0);
                a1 = fmaf(xv.w, w1s[(k + 3) * 64 + cl], a1);
            }
            const float y = fmaxf(a0 + a1 + bb, 0.f);
            atomicAdd(&g_Seg[__ldg(gid + row) * OUTD + c], y);
        }
        __syncthreads();
    }
}

// ---------------------------------------------------------------------------
// Kernel C: readout MLP, one block per graph.
// ---------------------------------------------------------------------------
extern "C" __global__ void __launch_bounds__(64, 8)
kC(const float* __restrict__ wr1, const float* __restrict__ br1,
   const float* __restrict__ wr2, const float* __restrict__ br2,
   const float* __restrict__ wr3, const float* __restrict__ br3,
   float* __restrict__ out)
{
    __shared__ float r1s[35];
    __shared__ float r2s[35];
    const int g = blockIdx.x, t = threadIdx.x;
    const float SC = 1.0507009873554805f;
    const float AL = 1.6732632423543772f;

    if (t < 35) {
        float acc = br1[t];
        #pragma unroll 4
        for (int k = 0; k < OUTD; ++k)
            acc = fmaf(g_Seg[g * OUTD + k], wr1[k * 35 + t], acc);
        r1s[t] = (acc > 0.f) ? SC * acc : SC * AL * (expf(acc) - 1.f);
    }
    __syncthreads();

    if (t < 35) {
        float acc = br2[t];
        #pragma unroll
        for (int k = 0; k < 35; ++k)
            acc = fmaf(r1s[k], wr2[k * 35 + t], acc);
        r2s[t] = (acc > 0.f) ? SC * acc : SC * AL * (expf(acc) - 1.f);
    }
    __syncthreads();

    if (t == 0) {
        float acc = br3[0];
        #pragma unroll
        for (int k = 0; k < 35; ++k)
            acc = fmaf(r2s[k], wr3[k], acc);
        out[g] = acc;
    }
}

// ---------------------------------------------------------------------------
extern "C" void kernel_launch(void* const* d_in, const int* in_sizes, int n_in,
                              void* d_out, int out_size)
{
    const float* h0  = (const float*)d_in[0];
    const float* h1  = (const float*)d_in[1];
    const float* h2  = (const float*)d_in[2];
    const float* w0  = (const float*)d_in[3];
    const float* b0  = (const float*)d_in[4];
    const float* w1  = (const float*)d_in[5];
    const float* b1  = (const float*)d_in[6];
    const float* wr1 = (const float*)d_in[7];
    const float* br1 = (const float*)d_in[8];
    const float* wr2 = (const float*)d_in[9];
    const float* br2 = (const float*)d_in[10];
    const float* wr3 = (const float*)d_in[11];
    const float* br3 = (const float*)d_in[12];
    const int*   gid = (const int*)d_in[13];

    const int smA = (16384 + 128 + 2 * 1408) * 4;   // 77312 B
    const int smB = (16384 + 1024) * 4;             // 69632 B
    cudaFuncSetAttribute(kA, cudaFuncAttributeMaxDynamicSharedMemorySize, smA);
    cudaFuncSetAttribute(kB, cudaFuncAttributeMaxDynamicSharedMemorySize, smB);

    kA<<<296, 256, smA>>>(h0, h1, h2, w0, b0);
    kB<<<444, 256, smB>>>(w1, b1, gid);
    kC<<<NGRAPH, 64>>>(wr1, br1, wr2, br2, wr3, br3, (float*)d_out);
}